// round 11
// baseline (speedup 1.0000x reference)
#include <cuda_runtime.h>

// Problem constants (fixed by reference setup_inputs)
#define B_  4
#define C_  3
#define H_  384
#define W_  1248
#define W8_ (W_/8)                    // 156 chunks of 8 floats per row
#define PLANE_ (H_*W_)                // 479232
#define OUT_PER_SIDE_ ((long long)B_*9*C_*H_*W_)  // 51,757,056
#define T_PER_SIDE_ (B_*C_*H_*W8_)                // 718,848 threads per side
#define NBLOCKS_ (2*T_PER_SIDE_/256)              // 5616 (exact)

// 256-bit streaming store (sm_100a+): one STG.256 -> warp writes 1KB contiguous.
__device__ __forceinline__ void stg256_cs(float* p, const float* w)
{
    asm volatile("st.global.cs.v8.f32 [%0], {%1,%2,%3,%4,%5,%6,%7,%8};"
                 :: "l"(p), "f"(w[0]), "f"(w[1]), "f"(w[2]), "f"(w[3]),
                    "f"(w[4]), "f"(w[5]), "f"(w[6]), "f"(w[7])
                 : "memory");
}

// out[b, (dy*3+dx)*C + c, y, x] = in[b, c, y+dy-1, x+dx-1]  (0 when OOB)
// Each thread produces an 8-wide x-chunk for all 9 (dy,dx) planes, one STG.256 each.
// Lane stride = 32B = store width -> warp bursts fully contiguous (1KB per wavefront).
// __launch_bounds__(256, 5): cap regs at 51 -> 5 CTAs/SM (~40 warps) to raise the
// number of in-flight store streams (R10 showed occupancy drives DRAM%).
// Last block writes the 81-element one-hot filter (eye(9) -> idx%10==0).
__global__ void __launch_bounds__(256, 5) unfold_kernel(
    const float* __restrict__ left,
    const float* __restrict__ right,
    float* __restrict__ out)
{
    if (blockIdx.x == NBLOCKS_) {
        int i = threadIdx.x;
        if (i < 81) out[2 * OUT_PER_SIDE_ + i] = (i % 10 == 0) ? 1.0f : 0.0f;
        return;
    }

    int t = blockIdx.x * 256 + threadIdx.x;   // exact fit: NBLOCKS_*256 == 2*T_PER_SIDE_

    const float* in = left;
    float* o = out;
    if (t >= T_PER_SIDE_) { t -= T_PER_SIDE_; in = right; o = out + OUT_PER_SIDE_; }

    int chunk = t % W8_;
    int rem   = t / W8_;
    int y     = rem % H_;
    rem      /= H_;
    int c     = rem % C_;
    int b     = rem / C_;
    int x     = chunk * 8;

    const float* base = in + ((b * C_ + c) * H_) * (long long)W_;

    // v[dy][0..9] = input[y+dy-1][x-1 .. x+8] with zero padding
    float v[3][10];
#pragma unroll
    for (int dy = 0; dy < 3; dy++) {
        int yy = y + dy - 1;
        if (yy < 0 || yy >= H_) {
#pragma unroll
            for (int i = 0; i < 10; i++) v[dy][i] = 0.f;
        } else {
            const float* row = base + yy * W_ + x;
            float4 a = *(const float4*)row;            // 32B-aligned
            float4 d = *(const float4*)(row + 4);
            v[dy][1] = a.x; v[dy][2] = a.y; v[dy][3] = a.z; v[dy][4] = a.w;
            v[dy][5] = d.x; v[dy][6] = d.y; v[dy][7] = d.z; v[dy][8] = d.w;
            v[dy][0] = (x > 0)       ? __ldg(row - 1) : 0.f;
            v[dy][9] = (x + 8 < W_)  ? __ldg(row + 8) : 0.f;
        }
    }

    // Output base for k=0 (channel index k*C + c)
    float* ob = o + ((((long long)b * 9 * C_ + c) * H_ + y) * W_ + x);

#pragma unroll
    for (int dy = 0; dy < 3; dy++) {
#pragma unroll
        for (int dx = 0; dx < 3; dx++) {
            float* p = ob + (long long)(dy * 3 + dx) * (C_ * PLANE_);
            stg256_cs(p, &v[dy][dx]);
        }
    }
}

extern "C" void kernel_launch(void* const* d_in, const int* in_sizes, int n_in,
                              void* d_out, int out_size)
{
    const float* left  = (const float*)d_in[0];
    const float* right = (const float*)d_in[1];
    float* out = (float*)d_out;

    unfold_kernel<<<NBLOCKS_ + 1, 256>>>(left, right, out);
}

// round 12
// speedup vs baseline: 1.0789x; 1.0789x over previous
#include <cuda_runtime.h>

// Problem constants (fixed by reference setup_inputs)
#define B_  4
#define C_  3
#define H_  384
#define W_  1248
#define W8_ (W_/8)                    // 156 chunks of 8 floats per row
#define PLANE_ (H_*W_)                // 479232
#define OUT_PER_SIDE_ ((long long)B_*9*C_*H_*W_)  // 51,757,056
#define T_PER_SIDE_ (B_*C_*H_*W8_)                // 718,848 threads per side
#define NBLOCKS_ (2*T_PER_SIDE_/256)              // 5616 (exact)

// 256-bit streaming store (sm_100a+): one STG.256 -> warp writes 1KB contiguous.
// .cs (evict-first): output is never re-read; keeps the 46MB of inputs L2-resident.
__device__ __forceinline__ void stg256_cs(float* p, const float* w)
{
    asm volatile("st.global.cs.v8.f32 [%0], {%1,%2,%3,%4,%5,%6,%7,%8};"
                 :: "l"(p), "f"(w[0]), "f"(w[1]), "f"(w[2]), "f"(w[3]),
                    "f"(w[4]), "f"(w[5]), "f"(w[6]), "f"(w[7])
                 : "memory");
}

// out[b, (dy*3+dx)*C + c, y, x] = in[b, c, y+dy-1, x+dx-1]  (0 when OOB)
// Each thread produces an 8-wide x-chunk for all 9 (dy,dx) planes, one STG.256 each.
// Lane stride = 32B = store width -> warp wavefronts are single 1KB contiguous bursts.
// Converged config (R6-R11 sweep): 8-wide/1-row tile, 256 threads, NO reg cap
// (62 regs / ~41% occ beats both higher-occ capped and larger-tile variants).
// Last block writes the 81-element one-hot filter (eye(9) -> idx%10==0).
__global__ void __launch_bounds__(256) unfold_kernel(
    const float* __restrict__ left,
    const float* __restrict__ right,
    float* __restrict__ out)
{
    if (blockIdx.x == NBLOCKS_) {
        int i = threadIdx.x;
        if (i < 81) out[2 * OUT_PER_SIDE_ + i] = (i % 10 == 0) ? 1.0f : 0.0f;
        return;
    }

    int t = blockIdx.x * 256 + threadIdx.x;   // exact fit: NBLOCKS_*256 == 2*T_PER_SIDE_

    const float* in = left;
    float* o = out;
    if (t >= T_PER_SIDE_) { t -= T_PER_SIDE_; in = right; o = out + OUT_PER_SIDE_; }

    int chunk = t % W8_;
    int rem   = t / W8_;
    int y     = rem % H_;
    rem      /= H_;
    int c     = rem % C_;
    int b     = rem / C_;
    int x     = chunk * 8;

    const float* base = in + ((b * C_ + c) * H_) * (long long)W_;

    // v[dy][0..9] = input[y+dy-1][x-1 .. x+8] with zero padding
    float v[3][10];
#pragma unroll
    for (int dy = 0; dy < 3; dy++) {
        int yy = y + dy - 1;
        if (yy < 0 || yy >= H_) {
#pragma unroll
            for (int i = 0; i < 10; i++) v[dy][i] = 0.f;
        } else {
            const float* row = base + yy * W_ + x;
            float4 a = *(const float4*)row;            // 32B-aligned
            float4 d = *(const float4*)(row + 4);
            v[dy][1] = a.x; v[dy][2] = a.y; v[dy][3] = a.z; v[dy][4] = a.w;
            v[dy][5] = d.x; v[dy][6] = d.y; v[dy][7] = d.z; v[dy][8] = d.w;
            v[dy][0] = (x > 0)       ? __ldg(row - 1) : 0.f;
            v[dy][9] = (x + 8 < W_)  ? __ldg(row + 8) : 0.f;
        }
    }

    // Output base for k=0 (channel index k*C + c)
    float* ob = o + ((((long long)b * 9 * C_ + c) * H_ + y) * W_ + x);

#pragma unroll
    for (int dy = 0; dy < 3; dy++) {
#pragma unroll
        for (int dx = 0; dx < 3; dx++) {
            float* p = ob + (long long)(dy * 3 + dx) * (C_ * PLANE_);
            stg256_cs(p, &v[dy][dx]);
        }
    }
}

extern "C" void kernel_launch(void* const* d_in, const int* in_sizes, int n_in,
                              void* d_out, int out_size)
{
    const float* left  = (const float*)d_in[0];
    const float* right = (const float*)d_in[1];
    float* out = (float*)d_out;

    unfold_kernel<<<NBLOCKS_ + 1, 256>>>(left, right, out);
}